// round 10
// baseline (speedup 1.0000x reference)
#include <cuda_runtime.h>
#include <cuda_fp16.h>
#include <math.h>

// ---------------- problem constants (fixed-shape problem) ----------------
#define NN 100000
#define EE 3200000
#define F_IN 128
#define HID 64
#define NLAYER 64
#define NCLASS 47
#define ALPHA 0.1f
#define THETA 0.5f

// ---------------- scratch (static device globals; no allocation) ---------
// Feature buffers hold PRE-SCALED rows:  hhat = dinv[r] * h[r]  (fp16).
// Row NN is a phantom all-zero row used to pad edge-chunk tails.
__device__ __align__(16) float  g_x0[NN * HID];          // relu(x@W1+b1), fp32
__device__ __align__(16) __half g_hA[(NN + 1) * HID];    // ping
__device__ __align__(16) __half g_hB[(NN + 1) * HID];    // pong
__device__ int   g_col[EE];          // CSR column indices
__device__ int   g_rowptr[NN + 1];
__device__ int   g_cnt[NN];          // zero at load; self-cleaned each run
__device__ int   g_cursor[NN];
__device__ float g_dinv[NN];         // 1/sqrt(deg+1)
__device__ float g_rdinv[NN];        // sqrt(deg+1)
__device__ int   g_bsum[128];
__device__ int   g_is64;

__device__ __forceinline__ const __half* pick_half(int s) {
    return (s == 1) ? g_hA : g_hB;
}
__device__ __forceinline__ __half* pick_half_mut(int s) {
    return (s == 1) ? g_hA : g_hB;
}

// packed f32x2 fma: d = a*b + d
__device__ __forceinline__ void fma2(unsigned long long& d,
                                     unsigned long long a,
                                     unsigned long long b) {
    asm("fma.rn.f32x2 %0, %1, %2, %0;" : "+l"(d) : "l"(a), "l"(b));
}

__device__ __forceinline__ int edge_at(const void* eiv, size_t idx, int is64) {
    if (is64) return (int)((const long long*)eiv)[idx];
    return ((const int*)eiv)[idx];
}

// consume 8 edges (one lane's feature-slice each) with fp16 pairwise tree:
// quad sums in fp16 (2 rounding levels), then fp32 accumulate.
__device__ __forceinline__ void consume8(const uint2 ha[8],
                                         float& a0, float& a1,
                                         float& a2, float& a3) {
    __half2 px0 = __hadd2(*(const __half2*)&ha[0].x, *(const __half2*)&ha[1].x);
    __half2 px1 = __hadd2(*(const __half2*)&ha[2].x, *(const __half2*)&ha[3].x);
    __half2 px2 = __hadd2(*(const __half2*)&ha[4].x, *(const __half2*)&ha[5].x);
    __half2 px3 = __hadd2(*(const __half2*)&ha[6].x, *(const __half2*)&ha[7].x);
    __half2 qx0 = __hadd2(px0, px1);
    __half2 qx1 = __hadd2(px2, px3);
    float2 fx0 = __half22float2(qx0);
    float2 fx1 = __half22float2(qx1);
    a0 += fx0.x; a0 += fx1.x;
    a1 += fx0.y; a1 += fx1.y;

    __half2 py0 = __hadd2(*(const __half2*)&ha[0].y, *(const __half2*)&ha[1].y);
    __half2 py1 = __hadd2(*(const __half2*)&ha[2].y, *(const __half2*)&ha[3].y);
    __half2 py2 = __hadd2(*(const __half2*)&ha[4].y, *(const __half2*)&ha[5].y);
    __half2 py3 = __hadd2(*(const __half2*)&ha[6].y, *(const __half2*)&ha[7].y);
    __half2 qy0 = __hadd2(py0, py1);
    __half2 qy1 = __hadd2(py2, py3);
    float2 fy0 = __half22float2(qy0);
    float2 fy1 = __half22float2(qy1);
    a2 += fy0.x; a2 += fy1.x;
    a3 += fy0.y; a3 += fy1.y;
}

// ---------------- x0 = relu(x @ W1 + b1)  (+ inline edge-dtype detect) ----
__global__ void __launch_bounds__(256) x0_kernel(const float* __restrict__ x,
                                                 const float* __restrict__ W1,
                                                 const float* __restrict__ b1,
                                                 const unsigned int* __restrict__ eip) {
    if (blockIdx.x == 0 && threadIdx.x == 0) {
        int all0 = 1;
        for (int i = 0; i < 64; i++) {
            if (eip[2 * i + 1] != 0u) { all0 = 0; break; }
        }
        g_is64 = all0;
    }

    __shared__ __align__(16) float Ws[F_IN * HID];  // 32KB
    int tid = threadIdx.x;
    const float4* W4 = (const float4*)W1;
    float4* Ws4 = (float4*)Ws;
#pragma unroll
    for (int i = tid; i < (F_IN * HID) / 4; i += 256) Ws4[i] = W4[i];
    __syncthreads();

    int base = blockIdx.x * 64;
    int w = tid >> 5, lane = tid & 31;
    float bx = b1[2 * lane], by = b1[2 * lane + 1];
#pragma unroll 1
    for (int i = 0; i < 8; i++) {
        int r = base + w * 8 + i;
        if (r >= NN) continue;
        float ax = bx, ay = by;
        const float4* xr = (const float4*)(x + (size_t)r * F_IN);
#pragma unroll 8
        for (int kk = 0; kk < F_IN / 4; kk++) {
            float4 xv = xr[kk];
            int k = kk * 4;
            float2 w0 = ((const float2*)(Ws + (k + 0) * HID))[lane];
            float2 w1 = ((const float2*)(Ws + (k + 1) * HID))[lane];
            float2 w2 = ((const float2*)(Ws + (k + 2) * HID))[lane];
            float2 w3 = ((const float2*)(Ws + (k + 3) * HID))[lane];
            ax += xv.x * w0.x; ay += xv.x * w0.y;
            ax += xv.y * w1.x; ay += xv.y * w1.y;
            ax += xv.z * w2.x; ay += xv.z * w2.y;
            ax += xv.w * w3.x; ay += xv.w * w3.y;
        }
        float vx = fmaxf(ax, 0.f), vy = fmaxf(ay, 0.f);
        ((float2*)(g_x0 + (size_t)r * HID))[lane] = make_float2(vx, vy);
    }
}

// ---------------- CSR: count ----------------
__global__ void count_kernel(const void* __restrict__ eiv) {
    int i = blockIdx.x * blockDim.x + threadIdx.x;
    int is64 = g_is64;
    if (i < EE) {
        int dst = edge_at(eiv, (size_t)EE + i, is64);
        atomicAdd(&g_cnt[dst], 1);
    }
}

// ---------------- CSR: block-local exclusive scan (1024 per block) -------
__global__ void scan1_kernel() {
    __shared__ int sh[256];
    int t = threadIdx.x, b = blockIdx.x;
    int base = b * 1024 + t * 4;
    int v0 = (base + 0 < NN) ? g_cnt[base + 0] : 0;
    int v1 = (base + 1 < NN) ? g_cnt[base + 1] : 0;
    int v2 = (base + 2 < NN) ? g_cnt[base + 2] : 0;
    int v3 = (base + 3 < NN) ? g_cnt[base + 3] : 0;
    int s0 = v0, s1 = s0 + v1, s2 = s1 + v2, s3 = s2 + v3;
    sh[t] = s3;
    __syncthreads();
    for (int off = 1; off < 256; off <<= 1) {
        int v = (t >= off) ? sh[t - off] : 0;
        __syncthreads();
        sh[t] += v;
        __syncthreads();
    }
    int excl = sh[t] - s3;
    if (base + 0 < NN) g_rowptr[base + 0] = excl;
    if (base + 1 < NN) g_rowptr[base + 1] = excl + s0;
    if (base + 2 < NN) g_rowptr[base + 2] = excl + s1;
    if (base + 3 < NN) g_rowptr[base + 3] = excl + s2;
    if (t == 255) g_bsum[b] = sh[255];
}

// ---------------- CSR: finalize (inline bsum prefix) + dinv + seed hA ----
__global__ void __launch_bounds__(256) scan3_kernel() {
    __shared__ int pre_sh;
    int t = threadIdx.x, b = blockIdx.x;
    if (t == 0) {
        int nb = b >> 2;
        int run = 0;
        for (int j = 0; j < nb; j++) run += g_bsum[j];
        pre_sh = run;
    }
    __syncthreads();
    int i = b * 256 + t;
    if (i < NN) {
        int rp = g_rowptr[i] + pre_sh;
        g_rowptr[i] = rp;
        g_cursor[i] = rp;
        int deg = g_cnt[i] + 1;
        float di = rsqrtf((float)deg);
        g_dinv[i] = di;
        g_rdinv[i] = sqrtf((float)deg);
        g_cnt[i] = 0;
        const float2* xr = (const float2*)(g_x0 + (size_t)i * HID);
        __half2* hw = (__half2*)(g_hA + (size_t)i * HID);
#pragma unroll
        for (int k = 0; k < 32; k++) {
            float2 v = xr[k];
            hw[k] = __floats2half2_rn(di * v.x, di * v.y);
        }
    }
    if (i == 0) g_rowptr[NN] = EE;
    if (b == 0 && t < 64) {
        g_hA[(size_t)NN * HID + t] = __float2half(0.f);
        g_hB[(size_t)NN * HID + t] = __float2half(0.f);
    }
}

// ---------------- CSR: scatter ----------------
__global__ void scatter_kernel(const void* __restrict__ eiv) {
    int i = blockIdx.x * blockDim.x + threadIdx.x;
    int is64 = g_is64;
    if (i < EE) {
        int src = edge_at(eiv, (size_t)i, is64);
        int dst = edge_at(eiv, (size_t)EE + i, is64);
        int pos = atomicAdd(&g_cursor[dst], 1);
        g_col[pos] = src;
    }
}

// ---------------- fused layer --------------------------------------------
__global__ void __launch_bounds__(256) layer_kernel(const float* __restrict__ Wl,
                                                    float beta, int sel_in, int sel_out) {
    __shared__ __align__(16) float Ws[HID * HID];    // 16KB
    __shared__ __align__(16) float ss[64 * 65];      // 16.6KB, pitch 65
    const __half* __restrict__ hin = pick_half(sel_in);
    __half* __restrict__ hout = pick_half_mut(sel_out);

    int tid = threadIdx.x;
    {   // stage Wl
        const float4* W4 = (const float4*)Wl;
        float4* Ws4 = (float4*)Ws;
#pragma unroll
        for (int i = tid; i < (HID * HID) / 4; i += 256) Ws4[i] = W4[i];
    }

    int base = blockIdx.x * 64;
    int w = tid >> 5, lane = tid & 31;
    int g = lane >> 4;          // edge parity group (0/1)
    int t = lane & 15;          // feature slot: features 4t..4t+3
    const unsigned FULL = 0xffffffffu;

    // warp-wide rowptr preload: lanes 0..8 hold rowptr[base+w*8 .. +8]
    int rp_lane = 0;
    {
        int idx = base + w * 8 + lane;
        if (idx > NN) idx = NN;
        if (lane < 9) rp_lane = g_rowptr[idx];
    }

    // -------- phase 1: warp-per-row unweighted gather --------
    // 32 cols loaded coalesced per chunk; edges processed in groups of 16
    // (8 pairs, 2 edges per LDG.64) with all 8 loads in flight before
    // consumption. fp16 quad-tree accumulate (2 rounding levels) -> fp32.
#pragma unroll 1
    for (int i = 0; i < 8; i++) {
        int rl = w * 8 + i;
        int r = base + rl;
        if (r < NN) {
            int e  = __shfl_sync(FULL, rp_lane, i);
            int e1 = __shfl_sync(FULL, rp_lane, i + 1);
            float a0 = 0.f, a1 = 0.f, a2 = 0.f, a3 = 0.f;
#pragma unroll 1
            while (e < e1) {
                int rem = e1 - e;
                int cw = (lane < rem) ? g_col[e + lane] : NN;
                int np = rem < 32 ? rem : 32;

                {   // group A: edges 0..15 (pairs 0..7)
                    uint2 ha[8];
#pragma unroll
                    for (int q = 0; q < 8; q++) {
                        int idx = 2 * q + g;
                        int c = __shfl_sync(FULL, cw, idx);
                        if (idx >= np) c = NN;
                        ha[q] = ((const uint2*)(hin + (size_t)c * HID))[t];
                    }
                    consume8(ha, a0, a1, a2, a3);
                }
                if (np > 16) {  // group B: edges 16..31 (pairs 8..15)
                    uint2 ha[8];
#pragma unroll
                    for (int q = 0; q < 8; q++) {
                        int idx = 16 + 2 * q + g;
                        int c = __shfl_sync(FULL, cw, idx);
                        if (idx >= np) c = NN;
                        ha[q] = ((const uint2*)(hin + (size_t)c * HID))[t];
                    }
                    consume8(ha, a0, a1, a2, a3);
                }
                e += 32;
            }
            // combine the two 16-lane halves
            a0 += __shfl_xor_sync(FULL, a0, 16);
            a1 += __shfl_xor_sync(FULL, a1, 16);
            a2 += __shfl_xor_sync(FULL, a2, 16);
            a3 += __shfl_xor_sync(FULL, a3, 16);
            // self loop: + hhat[r], then scale by dinv[r]
            uint2 hs = ((const uint2*)(hin + (size_t)r * HID))[t];
            float2 s0f = __half22float2(*(__half2*)&hs.x);
            float2 s1f = __half22float2(*(__half2*)&hs.y);
            a0 += s0f.x; a1 += s0f.y; a2 += s1f.x; a3 += s1f.y;
            float dr = g_dinv[r];
            float4 x0v = ((const float4*)(g_x0 + (size_t)r * HID))[t];
            if (lane < 16) {
                int bsh = rl * 65 + 4 * t;
                ss[bsh + 0] = (1.f - ALPHA) * (dr * a0) + ALPHA * x0v.x;
                ss[bsh + 1] = (1.f - ALPHA) * (dr * a1) + ALPHA * x0v.y;
                ss[bsh + 2] = (1.f - ALPHA) * (dr * a2) + ALPHA * x0v.z;
                ss[bsh + 3] = (1.f - ALPHA) * (dr * a3) + ALPHA * x0v.w;
            }
        }
    }
    __syncthreads();

    // -------- phase 2: 64x64 @ 64x64 GEMM from shared, packed f32x2 FMA ----
    int rl = tid & 63;
    int gq = tid >> 6;          // 4 groups of 16 columns
    int cbase = gq * 16;
    unsigned long long acc[8];
#pragma unroll
    for (int i = 0; i < 8; i++) acc[i] = 0ull;
#pragma unroll 8
    for (int k = 0; k < HID; k++) {
        float sk = ss[rl * 65 + k];
        unsigned long long skk;
        asm("mov.b64 %0, {%1, %2};" : "=l"(skk) : "f"(sk), "f"(sk));
        const ulonglong2* wp = (const ulonglong2*)(Ws + k * HID + cbase);  // warp-uniform
        ulonglong2 p0 = wp[0], p1 = wp[1], p2 = wp[2], p3 = wp[3];
        fma2(acc[0], p0.x, skk); fma2(acc[1], p0.y, skk);
        fma2(acc[2], p1.x, skk); fma2(acc[3], p1.y, skk);
        fma2(acc[4], p2.x, skk); fma2(acc[5], p2.y, skk);
        fma2(acc[6], p3.x, skk); fma2(acc[7], p3.y, skk);
    }
    int r = base + rl;
    if (r < NN) {
        float ob = 1.f - beta;
        float di = g_dinv[r];
        unsigned int u[8];
#pragma unroll
        for (int q = 0; q < 8; q++) {
            float lo, hi;
            asm("mov.b64 {%0, %1}, %2;" : "=f"(lo), "=f"(hi) : "l"(acc[q]));
            float v0 = fmaxf(ob * ss[rl * 65 + cbase + 2 * q + 0] + beta * lo, 0.f);
            float v1 = fmaxf(ob * ss[rl * 65 + cbase + 2 * q + 1] + beta * hi, 0.f);
            __half2 h2 = __floats2half2_rn(di * v0, di * v1);
            u[q] = *(unsigned int*)&h2;
        }
        uint4* dst = (uint4*)(hout + (size_t)r * HID + cbase);  // 32B-aligned
        dst[0] = make_uint4(u[0], u[1], u[2], u[3]);
        dst[1] = make_uint4(u[4], u[5], u[6], u[7]);
    }
}

// ---------------- logits + log_softmax ----------------
__global__ void __launch_bounds__(256) out_kernel(int sel_in,
                                                  const float* __restrict__ W2,
                                                  const float* __restrict__ b2,
                                                  float* __restrict__ out) {
    __shared__ float W2s[HID * NCLASS];
    __shared__ float b2s[NCLASS];
    __shared__ float hrow[8][HID];
    const __half* __restrict__ hin = pick_half(sel_in);

    int tid = threadIdx.x;
    for (int i = tid; i < HID * NCLASS; i += 256) W2s[i] = W2[i];
    if (tid < NCLASS) b2s[tid] = b2[tid];
    __syncthreads();

    int w = tid >> 5, lane = tid & 31;
    int r = blockIdx.x * 8 + w;
    if (r < NN) {
        float rdi = g_rdinv[r];
        hrow[w][lane] = rdi * __half2float(hin[(size_t)r * HID + lane]);
        hrow[w][lane + 32] = rdi * __half2float(hin[(size_t)r * HID + lane + 32]);
    }
    __syncwarp();
    if (r >= NN) return;

    int j0 = lane, j1 = lane + 32;
    bool has1 = (j1 < NCLASS);
    float a0 = b2s[j0];
    float a1 = has1 ? b2s[j1] : 0.f;
#pragma unroll 4
    for (int k = 0; k < HID; k++) {
        float hv = hrow[w][k];
        a0 += hv * W2s[k * NCLASS + j0];
        if (has1) a1 += hv * W2s[k * NCLASS + j1];
    }
    float m = a0;
    if (has1) m = fmaxf(m, a1);
#pragma unroll
    for (int off = 16; off; off >>= 1) m = fmaxf(m, __shfl_xor_sync(0xffffffffu, m, off));
    float s = expf(a0 - m) + (has1 ? expf(a1 - m) : 0.f);
#pragma unroll
    for (int off = 16; off; off >>= 1) s += __shfl_xor_sync(0xffffffffu, s, off);
    float lse = m + logf(s);
    out[(size_t)r * NCLASS + j0] = a0 - lse;
    if (has1) out[(size_t)r * NCLASS + j1] = a1 - lse;
}

// ---------------- launch ----------------
extern "C" void kernel_launch(void* const* d_in, const int* in_sizes, int n_in,
                              void* d_out, int out_size) {
    const float* x = (const float*)d_in[0];
    const void* ei = (const void*)d_in[1];
    const float* W1 = (const float*)d_in[2];
    const float* b1 = (const float*)d_in[3];
    const float* convW = (const float*)d_in[4];
    const float* W2 = (const float*)d_in[5];
    const float* b2 = (const float*)d_in[6];
    float* out = (float*)d_out;

    const int TB = 256;
    const int nblkN = (NN + TB - 1) / TB;      // 391
    const int nblkE = (EE + TB - 1) / TB;
    const int nscan = (NN + 1023) / 1024;      // 98
    const int nrowblk = (NN + 63) / 64;        // 1563

    x0_kernel<<<nrowblk, TB>>>(x, W1, b1, (const unsigned int*)ei);
    count_kernel<<<nblkE, TB>>>(ei);
    scan1_kernel<<<nscan, TB>>>();
    scan3_kernel<<<nblkN, TB>>>();
    scatter_kernel<<<nblkE, TB>>>(ei);

    int sel_in = 1;
    for (int l = 0; l < NLAYER; l++) {
        float beta = logf(THETA / (float)(l + 1) + 1.0f);
        int sel_out = 3 - sel_in;
        layer_kernel<<<nrowblk, TB>>>(convW + (size_t)l * HID * HID, beta, sel_in, sel_out);
        sel_in = sel_out;
    }

    out_kernel<<<(NN + 7) / 8, TB>>>(sel_in, W2, b2, out);
}